// round 14
// baseline (speedup 1.0000x reference)
#include <cuda_runtime.h>
#include <math.h>

#define BATCH 16
#define NSZ 320
#define NPIX (320*320)
#define NPLANES (BATCH*2)
#define TOTAL (NPLANES*NPIX)
#define S320 0.055901699437494740f   /* 1/sqrt(320) */

__device__ float g_z[TOTAL];
__device__ float g_x[TOTAL];
__device__ float g_t1[TOTAL];
__device__ float g_t2[TOTAL];
__device__ float2 g_tw[NSZ];

static __device__ __forceinline__ float2 cadd(float2 a, float2 b){ return make_float2(a.x+b.x, a.y+b.y); }
static __device__ __forceinline__ float2 csub(float2 a, float2 b){ return make_float2(a.x-b.x, a.y-b.y); }
static __device__ __forceinline__ float2 cmul(float2 a, float2 b){ return make_float2(a.x*b.x - a.y*b.y, a.x*b.y + a.y*b.x); }
static __device__ __forceinline__ float2 cmadd(float2 acc, float2 a, float2 b){
    acc.x += a.x*b.x - a.y*b.y;
    acc.y += a.x*b.y + a.y*b.x;
    return acc;
}

template<int INV>
static __device__ __forceinline__ float2 twf(const float2* __restrict__ tws, int idx){
    float2 w = tws[idx];
    if (INV) w.y = -w.y;
    return w;
}

template<int INV>
static __device__ __forceinline__ void bfly4(float2 a0, float2 a1, float2 a2, float2 a3,
                                             float2& b0, float2& b1, float2& b2, float2& b3){
    float2 s02 = cadd(a0,a2), d02 = csub(a0,a2);
    float2 s13 = cadd(a1,a3), d13 = csub(a1,a3);
    float2 jd  = INV ? make_float2(-d13.y, d13.x) : make_float2(d13.y, -d13.x);
    b0 = cadd(s02,s13); b1 = cadd(d02,jd); b2 = csub(s02,s13); b3 = csub(d02,jd);
}

// full 16-pt DFT in registers (natural order in/out); W16^t = W320^{20t}
template<int INV>
static __device__ __forceinline__ void dft16(float2* c, const float2* __restrict__ tws){
    float2 t[16];
    #pragma unroll
    for (int pp = 0; pp < 4; pp++){
        float2 b0,b1,b2,b3;
        bfly4<INV>(c[pp], c[pp+4], c[pp+8], c[pp+12], b0,b1,b2,b3);
        t[4*pp  ] = b0;
        t[4*pp+1] = cmul(b1, twf<INV>(tws, 20*pp));
        t[4*pp+2] = cmul(b2, twf<INV>(tws, 40*pp));
        t[4*pp+3] = cmul(b3, twf<INV>(tws, 60*pp));
    }
    #pragma unroll
    for (int q = 0; q < 4; q++){
        float2 b0,b1,b2,b3;
        bfly4<INV>(t[q], t[q+4], t[q+8], t[q+12], b0,b1,b2,b3);
        c[q] = b0; c[q+4] = b1; c[q+8] = b2; c[q+12] = b3;
    }
}

// full 20-pt DFT in registers (natural order in/out); W20^t = W320^{16t}, W5^t = W320^{64t}
template<int INV>
static __device__ __forceinline__ void dft20(float2* c, const float2* __restrict__ tws){
    float2 y[20];
    #pragma unroll
    for (int pp = 0; pp < 5; pp++){
        float2 b0,b1,b2,b3;
        bfly4<INV>(c[pp], c[pp+5], c[pp+10], c[pp+15], b0,b1,b2,b3);
        y[4*pp  ] = b0;
        y[4*pp+1] = cmul(b1, twf<INV>(tws, 16*pp));
        y[4*pp+2] = cmul(b2, twf<INV>(tws, 32*pp));
        y[4*pp+3] = cmul(b3, twf<INV>(tws, 48*pp));
    }
    float2 w1 = twf<INV>(tws,64), w2 = twf<INV>(tws,128), w3 = twf<INV>(tws,192), w4 = twf<INV>(tws,256);
    #pragma unroll
    for (int q2 = 0; q2 < 4; q2++){
        float2 a0=y[q2], a1=y[q2+4], a2=y[q2+8], a3=y[q2+12], a4=y[q2+16];
        float2 b0 = cadd(cadd(a0,a1), cadd(cadd(a2,a3), a4));
        float2 b1 = a0; b1=cmadd(b1,a1,w1); b1=cmadd(b1,a2,w2); b1=cmadd(b1,a3,w3); b1=cmadd(b1,a4,w4);
        float2 b2 = a0; b2=cmadd(b2,a1,w2); b2=cmadd(b2,a2,w4); b2=cmadd(b2,a3,w1); b2=cmadd(b2,a4,w3);
        float2 b3 = a0; b3=cmadd(b3,a1,w3); b3=cmadd(b3,a2,w1); b3=cmadd(b3,a3,w4); b3=cmadd(b3,a4,w2);
        float2 b4 = a0; b4=cmadd(b4,a1,w4); b4=cmadd(b4,a2,w3); b4=cmadd(b4,a3,w2); b4=cmadd(b4,a4,w1);
        c[q2]=b0; c[q2+4]=b1; c[q2+8]=b2; c[q2+12]=b3; c[q2+16]=b4;
    }
}

__global__ void init_tw_kernel()
{
    int j = threadIdx.x;
    double sv, cv;
    sincospi((double)j / 160.0, &sv, &cv);
    g_tw[j] = make_float2((float)cv, (float)(-sv));
}

// ------ Row-pass FFT: 8 rows/block, 160 threads, grid BATCH*40 ------
#define RSTR 322
template<int INV, bool DUAL>
__global__ void __launch_bounds__(160) fft_row_kernel(const float* __restrict__ in,
                                                      float* __restrict__ o1,
                                                      float* __restrict__ o2)
{
    __shared__ float sRe[8*RSTR];
    __shared__ float sIm[8*RSTR];
    __shared__ float2 tws[320];
    int tid = threadIdx.x;
    tws[tid] = g_tw[tid];
    tws[tid+160] = g_tw[tid+160];
    int b    = blockIdx.x / 40;
    int row0 = (blockIdx.x % 40) * 8;
    size_t pbase = (size_t)b*2*NPIX;

    int rA = tid / 20, p = tid - 20*rA;          // rA in [0,8), p in [0,20)
    const float* pr = in + pbase + (size_t)(row0 + rA)*NSZ;
    float sp = (p & 1) ? -1.f : 1.f;
    float2 c[20];
    #pragma unroll
    for (int k = 0; k < 16; k++){
        c[k].x = pr[p + 20*k] * sp;
        c[k].y = pr[NPIX + p + 20*k] * sp;
    }
    __syncthreads();
    dft16<INV>(c, tws);
    {
        float* re = sRe + rA*RSTR;
        float* im = sIm + rA*RSTR;
        #pragma unroll
        for (int f = 0; f < 16; f++){
            float2 v = cmul(c[f], twf<INV>(tws, f*p));
            re[f*20 + p] = v.x;
            im[f*20 + p] = v.y;
        }
    }
    __syncthreads();

    if (tid < 128){
        int rB = tid >> 4, q = tid & 15;         // rB in [0,8)
        const float* re = sRe + rB*RSTR;
        const float* im = sIm + rB*RSTR;
        #pragma unroll
        for (int k = 0; k < 20; k++){
            c[k].x = re[q*20 + k];
            c[k].y = im[q*20 + k];
        }
        dft20<INV>(c, tws);
        float osg = (q & 1) ? -S320 : S320;
        float* p1 = o1 + pbase + (size_t)(row0 + rB)*NSZ;
        #pragma unroll
        for (int f = 0; f < 20; f++){
            p1[q + 16*f]        = c[f].x*osg;
            p1[NPIX + q + 16*f] = c[f].y*osg;
        }
        if (DUAL){
            float* p2 = o2 + pbase + (size_t)(row0 + rB)*NSZ;
            #pragma unroll
            for (int f = 0; f < 20; f++){
                p2[q + 16*f]        = c[f].x*osg;
                p2[NPIX + q + 16*f] = c[f].y*osg;
            }
        }
    }
}

// ------ Col-pass: register-resident, 8 columns/block, 160 threads ------
#define CSTR 321

// init: inverse col FFT only (y -> out)
__global__ void __launch_bounds__(160) fft_col_init(const float* __restrict__ in,
                                                    float* __restrict__ out)
{
    __shared__ float sRe[8*CSTR];
    __shared__ float sIm[8*CSTR];
    __shared__ float2 tws[320];
    int tid = threadIdx.x;
    tws[tid] = g_tw[tid];
    tws[tid+160] = g_tw[tid+160];
    int b    = blockIdx.x / 40;
    int col0 = (blockIdx.x % 40) * 8;
    size_t pb = (size_t)b*2*NPIX;
    int c = tid & 7, p = tid >> 3;               // p in [0,20)
    const float* pr = in + pb + col0 + c;
    float sp = (p & 1) ? -1.f : 1.f;
    float2 v[20];
    #pragma unroll
    for (int k = 0; k < 16; k++){
        size_t ro = (size_t)(p + 20*k)*NSZ;
        v[k].x = pr[ro] * sp;
        v[k].y = pr[NPIX + ro] * sp;
    }
    __syncthreads();
    dft16<1>(v, tws);
    {
        float* re = sRe + c*CSTR;
        float* im = sIm + c*CSTR;
        #pragma unroll
        for (int f = 0; f < 16; f++){
            float2 w = cmul(v[f], twf<1>(tws, f*p));
            re[f*20 + p] = w.x;
            im[f*20 + p] = w.y;
        }
    }
    __syncthreads();
    if (tid < 128){
        int q = tid >> 3;                        // [0,16)
        const float* re = sRe + c*CSTR;
        const float* im = sIm + c*CSTR;
        #pragma unroll
        for (int k = 0; k < 20; k++){
            v[k].x = re[q*20 + k];
            v[k].y = im[q*20 + k];
        }
        dft20<1>(v, tws);
        float osg = (q & 1) ? -S320 : S320;
        float* po = out + pb + col0 + c;
        #pragma unroll
        for (int f = 0; f < 20; f++){
            size_t ro = (size_t)(q + 16*f)*NSZ;
            po[ro]        = v[f].x*osg;
            po[NPIX + ro] = v[f].y*osg;
        }
    }
}

// combine: forward col FFT -> k-space data consistency -> inverse col FFT
__global__ void __launch_bounds__(160) fft_col_combine(const float* __restrict__ in,
                                                       const float* __restrict__ yk,
                                                       const float* __restrict__ mask,
                                                       float* __restrict__ out)
{
    __shared__ float sRe[8*CSTR];
    __shared__ float sIm[8*CSTR];
    __shared__ float2 tws[320];
    int tid = threadIdx.x;
    tws[tid] = g_tw[tid];
    tws[tid+160] = g_tw[tid+160];
    int b    = blockIdx.x / 40;
    int col0 = (blockIdx.x % 40) * 8;
    size_t pb = (size_t)b*2*NPIX;
    int c = tid & 7, p = tid >> 3;               // p in [0,20)
    const float* pr = in + pb + col0 + c;
    float sp = (p & 1) ? -1.f : 1.f;
    float2 v[20];
    #pragma unroll
    for (int k = 0; k < 16; k++){
        size_t ro = (size_t)(p + 20*k)*NSZ;
        v[k].x = pr[ro] * sp;
        v[k].y = pr[NPIX + ro] * sp;
    }
    __syncthreads();
    dft16<0>(v, tws);
    {
        float* re = sRe + c*CSTR;
        float* im = sIm + c*CSTR;
        #pragma unroll
        for (int f = 0; f < 16; f++){
            float2 w = cmul(v[f], twf<0>(tws, f*p));
            re[f*20 + p] = w.x;
            im[f*20 + p] = w.y;
        }
    }
    __syncthreads();

    bool actB = tid < 128;
    int q = tid >> 3;                            // [0,16) when actB
    if (actB){
        const float* re = sRe + c*CSTR;
        const float* im = sIm + c*CSTR;
        #pragma unroll
        for (int k = 0; k < 20; k++){
            v[k].x = re[q*20 + k];
            v[k].y = im[q*20 + k];
        }
    }
    __syncthreads();     // all reads done before re-writing smem
    if (actB){
        dft20<0>(v, tws);
        float sq  = (q & 1) ? -1.f : 1.f;
        float sgs = sq * S320;
        const float* mp = mask + (size_t)b*NPIX + col0 + c;
        const float* yp = yk + pb + col0 + c;
        #pragma unroll
        for (int f = 0; f < 20; f++){
            size_t ro = (size_t)(q + 16*f)*NSZ;
            float m  = mp[ro];
            float yr = yp[ro];
            float yi = yp[NPIX + ro];
            float Kx = v[f].x * sgs, Ky = v[f].y * sgs;
            Kx += m*(yr - Kx);
            Ky += m*(yi - Ky);
            v[f].x = Kx * sq;
            v[f].y = Ky * sq;
        }
        dft20<1>(v, tws);
        float* re = sRe + c*CSTR;
        float* im = sIm + c*CSTR;
        #pragma unroll
        for (int m = 0; m < 20; m++){
            float2 w = cmul(v[m], twf<1>(tws, m*q));
            re[m*16 + q] = w.x;
            im[m*16 + q] = w.y;
        }
    }
    __syncthreads();

    {
        int m = tid >> 3;                        // [0,20)
        const float* re = sRe + c*CSTR;
        const float* im = sIm + c*CSTR;
        #pragma unroll
        for (int kq = 0; kq < 16; kq++){
            v[kq].x = re[m*16 + kq];
            v[kq].y = im[m*16 + kq];
        }
        dft16<1>(v, tws);
        float so = (m & 1) ? -S320 : S320;
        float* po = out + pb + col0 + c;
        #pragma unroll
        for (int j = 0; j < 16; j++){
            size_t ro = (size_t)(m + 20*j)*NSZ;
            po[ro]        = v[j].x*so;
            po[NPIX + ro] = v[j].y*so;
        }
    }
}

// ----------- fused TV prox (register 2x2 patches) + warp-Haar + momentum
#define RG 42
#define IS2 0.70710678118654752f
static __device__ __forceinline__ float softf(float v){
    float m = fabsf(v) - 0.005f;
    m = fmaxf(m, 0.f);
    return copysignf(m, v);
}

__global__ void __launch_bounds__(448, 3) tvwav_kernel(const float* __restrict__ in,
                                                       const float* __restrict__ xold,
                                                       float* __restrict__ xnew,
                                                       float* __restrict__ znew,
                                                       float beta)
{
    __shared__ float sUL [RG*21];
    __shared__ float sUT [21*43];
    __shared__ float sPxR[RG*21];
    __shared__ float sPyB[21*43];
    __shared__ float sw  [32*33];

    int tid = threadIdx.x;
    bool act = tid < 441;
    int pr = tid / 21, pc = tid - pr*21;
    int ri = 2*pr, rj = 2*pc;
    int plane = blockIdx.z;
    int gx0 = blockIdx.x*32 - 5;
    int gy0 = blockIdx.y*32 - 5;
    int base = plane * NPIX;
    int gi0 = gy0 + ri, gj0 = gx0 + rj;

    float x[2][2], u[2][2], px[2][2], py[2][2];

    if (act){
        #pragma unroll
        for (int i = 0; i < 2; i++){
            #pragma unroll
            for (int j = 0; j < 2; j++){
                int gi = gi0 + i, gj = gj0 + j;
                float v = 0.f;
                if ((unsigned)gi < NSZ && (unsigned)gj < NSZ) v = in[base + gi*NSZ + gj];
                x[i][j] = v; u[i][j] = v;
                px[i][j] = 0.f; py[i][j] = 0.f;
            }
        }
        sUL[ ri   *21 + pc] = u[0][0];
        sUL[(ri+1)*21 + pc] = u[1][0];
        sUT[pr*43 + rj    ] = u[0][0];
        sUT[pr*43 + rj + 1] = u[0][1];
    }
    __syncthreads();

    const float lam = 0.005f, tau = 0.25f;
    #pragma unroll 1
    for (int it = 0; it < 5; it++){
        if (act){
            bool xok1 = (rj + 1 < RG-1) && (gj0 + 1 < NSZ-1);
            bool yok1 = (ri + 1 < RG-1) && (gi0 + 1 < NSZ-1);
            float uR0 = xok1 ? sUL[ ri   *21 + pc + 1] : 0.f;
            float uR1 = xok1 ? sUL[(ri+1)*21 + pc + 1] : 0.f;
            float uD0 = yok1 ? sUT[(pr+1)*43 + rj    ] : 0.f;
            float uD1 = yok1 ? sUT[(pr+1)*43 + rj + 1] : 0.f;
            #pragma unroll
            for (int i = 0; i < 2; i++){
                #pragma unroll
                for (int j = 0; j < 2; j++){
                    bool xok = (j == 0) ? ((gj0 < NSZ-1)) : xok1;
                    bool yok = (i == 0) ? ((gi0 < NSZ-1)) : yok1;
                    float gx = 0.f, gy = 0.f;
                    if (xok) gx = ((j == 0) ? u[i][1] : ((i == 0) ? uR0 : uR1)) - u[i][j];
                    if (yok) gy = ((i == 0) ? u[1][j] : ((j == 0) ? uD0 : uD1)) - u[i][j];
                    float pnx = fmaf(tau, gx, px[i][j]);
                    float pny = fmaf(tau, gy, py[i][j]);
                    float s  = fmaf(pnx, pnx, fmaf(pny, pny, 1e-8f));
                    float sc = (s > 1.f) ? rsqrtf(s) : 1.f;
                    px[i][j] = pnx*sc;
                    py[i][j] = pny*sc;
                }
            }
            sPxR[ ri   *21 + pc] = px[0][1];
            sPxR[(ri+1)*21 + pc] = px[1][1];
            sPyB[pr*43 + rj    ] = py[1][0];
            sPyB[pr*43 + rj + 1] = py[1][1];
        }
        __syncthreads();
        if (act){
            float pxL0 = (pc > 0) ? sPxR[ ri   *21 + pc - 1] : 0.f;
            float pxL1 = (pc > 0) ? sPxR[(ri+1)*21 + pc - 1] : 0.f;
            float pyU0 = (pr > 0) ? sPyB[(pr-1)*43 + rj    ] : 0.f;
            float pyU1 = (pr > 0) ? sPyB[(pr-1)*43 + rj + 1] : 0.f;
            #pragma unroll
            for (int i = 0; i < 2; i++){
                #pragma unroll
                for (int j = 0; j < 2; j++){
                    float pxl = (j == 1) ? px[i][0] : ((i == 0) ? pxL0 : pxL1);
                    float pyu = (i == 1) ? py[0][j] : ((j == 0) ? pyU0 : pyU1);
                    int gj = gj0 + j, gi = gi0 + i;
                    float dvx = (gj == 0) ? px[i][j] : ((gj == NSZ-1) ? -pxl : px[i][j] - pxl);
                    float dvy = (gi == 0) ? py[i][j] : ((gi == NSZ-1) ? -pyu : py[i][j] - pyu);
                    u[i][j] = x[i][j] - lam*(dvx + dvy);
                }
            }
        }
        if (it < 4){
            if (act){
                sUL[ ri   *21 + pc] = u[0][0];
                sUL[(ri+1)*21 + pc] = u[1][0];
                sUT[pr*43 + rj    ] = u[0][0];
                sUT[pr*43 + rj + 1] = u[0][1];
            }
            __syncthreads();
        }
    }

    if (act){
        #pragma unroll
        for (int i = 0; i < 2; i++){
            #pragma unroll
            for (int j = 0; j < 2; j++){
                int ti = ri + i - 5, tj = rj + j - 5;
                if (ti >= 0 && ti < 32 && tj >= 0 && tj < 32)
                    sw[ti*33 + tj] = u[i][j];
            }
        }
    }
    __syncthreads();

    {
        const unsigned FM = 0xffffffffu;
        int lane = tid & 31;
        int warp = tid >> 5;
        int l = lane & 15;
        int qi = l >> 2, qj = l & 3;
        int pi = qi & 1, pj = qj & 1;
        int Pi = (qi >> 1) & 1, Pj = (qj >> 1) & 1;
        for (int blk = warp; blk < 16; blk += 14){
            int r0 = (blk >> 2)*8 + 2*qi;
            int c0 = (blk & 3)*8 + 2*qj;
            float p00 = sw[r0*33 + c0],     p01 = sw[r0*33 + c0 + 1];
            float p10 = sw[(r0+1)*33 + c0], p11 = sw[(r0+1)*33 + c0 + 1];
            float s0 = (p00 + p01)*IS2, d0 = (p00 - p01)*IS2;
            float s1 = (p10 + p11)*IS2, d1 = (p10 - p11)*IS2;
            float ll1 = (s0 + s1)*IS2;
            float lh1 = softf((s0 - s1)*IS2);
            float hl1 = softf((d0 + d1)*IS2);
            float hh1 = softf((d0 - d1)*IS2);
            float b  = __shfl_xor_sync(FM, ll1, 1);
            float cl = (ll1 + b)*IS2;
            float cd = (pj ? (b - ll1) : (ll1 - b))*IS2;
            float rl = __shfl_xor_sync(FM, cl, 4);
            float rd = __shfl_xor_sync(FM, cd, 4);
            float ll2 = (cl + rl)*IS2;
            float lh2 = softf((pi ? (rl - cl) : (cl - rl))*IS2);
            float hl2 = softf((cd + rd)*IS2);
            float hh2 = softf((pi ? (rd - cd) : (cd - rd))*IS2);
            float b3  = __shfl_xor_sync(FM, ll2, 2);
            float cl3 = (ll2 + b3)*IS2;
            float cd3 = (Pj ? (b3 - ll2) : (ll2 - b3))*IS2;
            float rl3 = __shfl_xor_sync(FM, cl3, 8);
            float rd3 = __shfl_xor_sync(FM, cd3, 8);
            float ll3 = (cl3 + rl3)*IS2;
            float lh3 = softf((Pi ? (rl3 - cl3) : (cl3 - rl3))*IS2);
            float hl3 = softf((cd3 + rd3)*IS2);
            float hh3 = softf((Pi ? (rd3 - cd3) : (cd3 - rd3))*IS2);
            float s3 = (Pi ? (ll3 - lh3) : (ll3 + lh3))*IS2;
            float d3 = (Pi ? (hl3 - hh3) : (hl3 + hh3))*IS2;
            float ll2r = (Pj ? (s3 - d3) : (s3 + d3))*IS2;
            float s2 = (pi ? (ll2r - lh2) : (ll2r + lh2))*IS2;
            float d2 = (pi ? (hl2 - hh2) : (hl2 + hh2))*IS2;
            float ll1r = (pj ? (s2 - d2) : (s2 + d2))*IS2;
            float sa = (ll1r + lh1)*IS2, sb = (ll1r - lh1)*IS2;
            float da = (hl1 + hh1)*IS2, db = (hl1 - hh1)*IS2;
            float q00 = (sa + da)*IS2, q01 = (sa - da)*IS2;
            float q10 = (sb + db)*IS2, q11 = (sb - db)*IS2;
            if (lane < 16){
                int gi = gy0 + 5 + r0, gj = gx0 + 5 + c0;
                int g = base + gi*NSZ + gj;
                float2 xo0 = *reinterpret_cast<const float2*>(xold + g);
                float2 xo1 = *reinterpret_cast<const float2*>(xold + g + NSZ);
                *reinterpret_cast<float2*>(xnew + g)       = make_float2(q00, q01);
                *reinterpret_cast<float2*>(xnew + g + NSZ) = make_float2(q10, q11);
                *reinterpret_cast<float2*>(znew + g) =
                    make_float2(q00 + beta*(q00 - xo0.x), q01 + beta*(q01 - xo0.y));
                *reinterpret_cast<float2*>(znew + g + NSZ) =
                    make_float2(q10 + beta*(q10 - xo1.x), q11 + beta*(q11 - xo1.y));
            }
        }
    }
}

// ----------------------------- host ------------------------------------
extern "C" void kernel_launch(void* const* d_in, const int* in_sizes, int n_in,
                              void* d_out, int out_size)
{
    const float* y    = (const float*)d_in[0];
    const float* mask = (const float*)d_in[1];
    float* out = (float*)d_out;
    float *z, *x, *t1, *t2;
    cudaGetSymbolAddress((void**)&z,   g_z);
    cudaGetSymbolAddress((void**)&x,   g_x);
    cudaGetSymbolAddress((void**)&t1,  g_t1);
    cudaGetSymbolAddress((void**)&t2,  g_t2);

    init_tw_kernel<<<1, 320>>>();

    // x0 = z0 = ifft2c(y)
    fft_col_init<<<BATCH*40, 160>>>(y, t1);
    fft_row_kernel<1,true ><<<BATCH*40, 160>>>(t1, x, z);

    double tt = 1.0;
    for (int it = 0; it < 15; it++){
        fft_row_kernel<0,false><<<BATCH*40, 160>>>(z, t1, nullptr);
        fft_col_combine<<<BATCH*40, 160>>>(t1, y, mask, t2);
        fft_row_kernel<1,false><<<BATCH*40, 160>>>(t2, t1, nullptr);
        double tn = 0.5*(1.0 + sqrt(1.0 + 4.0*tt*tt));
        float beta = (float)((tt - 1.0)/tn);
        float* xdst = (it == 14) ? out : x;
        tvwav_kernel<<<dim3(10,10,32), 448>>>(t1, x, xdst, z, beta);
        tt = tn;
    }
}

// round 15
// speedup vs baseline: 1.0224x; 1.0224x over previous
#include <cuda_runtime.h>
#include <math.h>

#define BATCH 16
#define NSZ 320
#define NPIX (320*320)
#define NPLANES (BATCH*2)
#define TOTAL (NPLANES*NPIX)
#define S320 0.055901699437494740f   /* 1/sqrt(320) */

__device__ float g_z[TOTAL];
__device__ float g_x[TOTAL];
__device__ float g_t1[TOTAL];
__device__ float g_t2[TOTAL];
__device__ float2 g_tw[NSZ];

static __device__ __forceinline__ float2 cadd(float2 a, float2 b){ return make_float2(a.x+b.x, a.y+b.y); }
static __device__ __forceinline__ float2 csub(float2 a, float2 b){ return make_float2(a.x-b.x, a.y-b.y); }
static __device__ __forceinline__ float2 cmul(float2 a, float2 b){ return make_float2(a.x*b.x - a.y*b.y, a.x*b.y + a.y*b.x); }
static __device__ __forceinline__ float2 cmadd(float2 acc, float2 a, float2 b){
    acc.x += a.x*b.x - a.y*b.y;
    acc.y += a.x*b.y + a.y*b.x;
    return acc;
}

template<int INV>
static __device__ __forceinline__ float2 twf(const float2* __restrict__ tws, int idx){
    float2 w = tws[idx];
    if (INV) w.y = -w.y;
    return w;
}

template<int INV>
static __device__ __forceinline__ void bfly4(float2 a0, float2 a1, float2 a2, float2 a3,
                                             float2& b0, float2& b1, float2& b2, float2& b3){
    float2 s02 = cadd(a0,a2), d02 = csub(a0,a2);
    float2 s13 = cadd(a1,a3), d13 = csub(a1,a3);
    float2 jd  = INV ? make_float2(-d13.y, d13.x) : make_float2(d13.y, -d13.x);
    b0 = cadd(s02,s13); b1 = cadd(d02,jd); b2 = csub(s02,s13); b3 = csub(d02,jd);
}

// full 16-pt DFT in registers (natural order in/out); W16^t = W320^{20t}
template<int INV>
static __device__ __forceinline__ void dft16(float2* c, const float2* __restrict__ tws){
    float2 t[16];
    #pragma unroll
    for (int pp = 0; pp < 4; pp++){
        float2 b0,b1,b2,b3;
        bfly4<INV>(c[pp], c[pp+4], c[pp+8], c[pp+12], b0,b1,b2,b3);
        t[4*pp  ] = b0;
        t[4*pp+1] = cmul(b1, twf<INV>(tws, 20*pp));
        t[4*pp+2] = cmul(b2, twf<INV>(tws, 40*pp));
        t[4*pp+3] = cmul(b3, twf<INV>(tws, 60*pp));
    }
    #pragma unroll
    for (int q = 0; q < 4; q++){
        float2 b0,b1,b2,b3;
        bfly4<INV>(t[q], t[q+4], t[q+8], t[q+12], b0,b1,b2,b3);
        c[q] = b0; c[q+4] = b1; c[q+8] = b2; c[q+12] = b3;
    }
}

// full 20-pt DFT in registers (natural order in/out); W20^t = W320^{16t}, W5^t = W320^{64t}
template<int INV>
static __device__ __forceinline__ void dft20(float2* c, const float2* __restrict__ tws){
    float2 y[20];
    #pragma unroll
    for (int pp = 0; pp < 5; pp++){
        float2 b0,b1,b2,b3;
        bfly4<INV>(c[pp], c[pp+5], c[pp+10], c[pp+15], b0,b1,b2,b3);
        y[4*pp  ] = b0;
        y[4*pp+1] = cmul(b1, twf<INV>(tws, 16*pp));
        y[4*pp+2] = cmul(b2, twf<INV>(tws, 32*pp));
        y[4*pp+3] = cmul(b3, twf<INV>(tws, 48*pp));
    }
    float2 w1 = twf<INV>(tws,64), w2 = twf<INV>(tws,128), w3 = twf<INV>(tws,192), w4 = twf<INV>(tws,256);
    #pragma unroll
    for (int q2 = 0; q2 < 4; q2++){
        float2 a0=y[q2], a1=y[q2+4], a2=y[q2+8], a3=y[q2+12], a4=y[q2+16];
        float2 b0 = cadd(cadd(a0,a1), cadd(cadd(a2,a3), a4));
        float2 b1 = a0; b1=cmadd(b1,a1,w1); b1=cmadd(b1,a2,w2); b1=cmadd(b1,a3,w3); b1=cmadd(b1,a4,w4);
        float2 b2 = a0; b2=cmadd(b2,a1,w2); b2=cmadd(b2,a2,w4); b2=cmadd(b2,a3,w1); b2=cmadd(b2,a4,w3);
        float2 b3 = a0; b3=cmadd(b3,a1,w3); b3=cmadd(b3,a2,w1); b3=cmadd(b3,a3,w4); b3=cmadd(b3,a4,w2);
        float2 b4 = a0; b4=cmadd(b4,a1,w4); b4=cmadd(b4,a2,w3); b4=cmadd(b4,a3,w2); b4=cmadd(b4,a4,w1);
        c[q2]=b0; c[q2+4]=b1; c[q2+8]=b2; c[q2+12]=b3; c[q2+16]=b4;
    }
}

__global__ void init_tw_kernel()
{
    int j = threadIdx.x;
    double sv, cv;
    sincospi((double)j / 160.0, &sv, &cv);
    g_tw[j] = make_float2((float)cv, (float)(-sv));
}

// ------ Row-pass FFT: 8 rows/block, 160 threads, grid BATCH*40 (R14 best) ------
#define RSTR 322
template<int INV, bool DUAL>
__global__ void __launch_bounds__(160) fft_row_kernel(const float* __restrict__ in,
                                                      float* __restrict__ o1,
                                                      float* __restrict__ o2)
{
    __shared__ float sRe[8*RSTR];
    __shared__ float sIm[8*RSTR];
    __shared__ float2 tws[320];
    int tid = threadIdx.x;
    tws[tid] = g_tw[tid];
    tws[tid+160] = g_tw[tid+160];
    int b    = blockIdx.x / 40;
    int row0 = (blockIdx.x % 40) * 8;
    size_t pbase = (size_t)b*2*NPIX;

    int rA = tid / 20, p = tid - 20*rA;          // rA in [0,8), p in [0,20)
    const float* pr = in + pbase + (size_t)(row0 + rA)*NSZ;
    float sp = (p & 1) ? -1.f : 1.f;
    float2 c[20];
    #pragma unroll
    for (int k = 0; k < 16; k++){
        c[k].x = pr[p + 20*k] * sp;
        c[k].y = pr[NPIX + p + 20*k] * sp;
    }
    __syncthreads();
    dft16<INV>(c, tws);
    {
        float* re = sRe + rA*RSTR;
        float* im = sIm + rA*RSTR;
        #pragma unroll
        for (int f = 0; f < 16; f++){
            float2 v = cmul(c[f], twf<INV>(tws, f*p));
            re[f*20 + p] = v.x;
            im[f*20 + p] = v.y;
        }
    }
    __syncthreads();

    if (tid < 128){
        int rB = tid >> 4, q = tid & 15;         // rB in [0,8)
        const float* re = sRe + rB*RSTR;
        const float* im = sIm + rB*RSTR;
        #pragma unroll
        for (int k = 0; k < 20; k++){
            c[k].x = re[q*20 + k];
            c[k].y = im[q*20 + k];
        }
        dft20<INV>(c, tws);
        float osg = (q & 1) ? -S320 : S320;
        float* p1 = o1 + pbase + (size_t)(row0 + rB)*NSZ;
        #pragma unroll
        for (int f = 0; f < 20; f++){
            p1[q + 16*f]        = c[f].x*osg;
            p1[NPIX + q + 16*f] = c[f].y*osg;
        }
        if (DUAL){
            float* p2 = o2 + pbase + (size_t)(row0 + rB)*NSZ;
            #pragma unroll
            for (int f = 0; f < 20; f++){
                p2[q + 16*f]        = c[f].x*osg;
                p2[NPIX + q + 16*f] = c[f].y*osg;
            }
        }
    }
}

// ------ Col-pass: register-resident, 16 columns/block, 320 threads (R13 best) ------
#define CSTR 321

// init: inverse col FFT only (y -> out)
__global__ void __launch_bounds__(320) fft_col_init(const float* __restrict__ in,
                                                    float* __restrict__ out)
{
    __shared__ float sRe[16*CSTR];
    __shared__ float sIm[16*CSTR];
    __shared__ float2 tws[320];
    int tid = threadIdx.x;
    tws[tid] = g_tw[tid];
    int b    = blockIdx.x / 20;
    int col0 = (blockIdx.x % 20) * 16;
    size_t pb = (size_t)b*2*NPIX;
    int c = tid & 15, p = tid >> 4;           // p in [0,20)
    const float* pr = in + pb + col0 + c;
    float sp = (p & 1) ? -1.f : 1.f;
    float2 v[20];
    #pragma unroll
    for (int k = 0; k < 16; k++){
        size_t ro = (size_t)(p + 20*k)*NSZ;
        v[k].x = pr[ro] * sp;
        v[k].y = pr[NPIX + ro] * sp;
    }
    __syncthreads();
    dft16<1>(v, tws);
    {
        float* re = sRe + c*CSTR;
        float* im = sIm + c*CSTR;
        #pragma unroll
        for (int f = 0; f < 16; f++){
            float2 w = cmul(v[f], twf<1>(tws, f*p));
            re[f*20 + p] = w.x;
            im[f*20 + p] = w.y;
        }
    }
    __syncthreads();
    if (tid < 256){
        int q = tid >> 4;                     // [0,16)
        const float* re = sRe + c*CSTR;
        const float* im = sIm + c*CSTR;
        #pragma unroll
        for (int k = 0; k < 20; k++){
            v[k].x = re[q*20 + k];
            v[k].y = im[q*20 + k];
        }
        dft20<1>(v, tws);
        float osg = (q & 1) ? -S320 : S320;
        float* po = out + pb + col0 + c;
        #pragma unroll
        for (int f = 0; f < 20; f++){
            size_t ro = (size_t)(q + 16*f)*NSZ;
            po[ro]        = v[f].x*osg;
            po[NPIX + ro] = v[f].y*osg;
        }
    }
}

// combine: forward col FFT -> k-space data consistency -> inverse col FFT
__global__ void __launch_bounds__(320) fft_col_combine(const float* __restrict__ in,
                                                       const float* __restrict__ yk,
                                                       const float* __restrict__ mask,
                                                       float* __restrict__ out)
{
    __shared__ float sRe[16*CSTR];
    __shared__ float sIm[16*CSTR];
    __shared__ float2 tws[320];
    int tid = threadIdx.x;
    tws[tid] = g_tw[tid];
    int b    = blockIdx.x / 20;
    int col0 = (blockIdx.x % 20) * 16;
    size_t pb = (size_t)b*2*NPIX;
    int c = tid & 15, p = tid >> 4;           // p in [0,20)
    const float* pr = in + pb + col0 + c;
    float sp = (p & 1) ? -1.f : 1.f;
    float2 v[20];
    #pragma unroll
    for (int k = 0; k < 16; k++){
        size_t ro = (size_t)(p + 20*k)*NSZ;
        v[k].x = pr[ro] * sp;
        v[k].y = pr[NPIX + ro] * sp;
    }
    __syncthreads();
    dft16<0>(v, tws);
    {
        float* re = sRe + c*CSTR;
        float* im = sIm + c*CSTR;
        #pragma unroll
        for (int f = 0; f < 16; f++){
            float2 w = cmul(v[f], twf<0>(tws, f*p));
            re[f*20 + p] = w.x;
            im[f*20 + p] = w.y;
        }
    }
    __syncthreads();

    bool actB = tid < 256;
    int q = tid >> 4;                          // [0,16) when actB
    if (actB){
        const float* re = sRe + c*CSTR;
        const float* im = sIm + c*CSTR;
        #pragma unroll
        for (int k = 0; k < 20; k++){
            v[k].x = re[q*20 + k];
            v[k].y = im[q*20 + k];
        }
    }
    __syncthreads();     // all reads done before re-writing smem
    if (actB){
        dft20<0>(v, tws);
        // v[f] = F_raw[q+16f]; data consistency in true centered k-space
        float sq  = (q & 1) ? -1.f : 1.f;
        float sgs = sq * S320;
        const float* mp = mask + (size_t)b*NPIX + col0 + c;
        const float* yp = yk + pb + col0 + c;
        #pragma unroll
        for (int f = 0; f < 20; f++){
            size_t ro = (size_t)(q + 16*f)*NSZ;
            float m  = mp[ro];
            float yr = yp[ro];
            float yi = yp[NPIX + ro];
            float Kx = v[f].x * sgs, Ky = v[f].y * sgs;
            Kx += m*(yr - Kx);
            Ky += m*(yi - Ky);
            v[f].x = Kx * sq;
            v[f].y = Ky * sq;
        }
        // inverse stage A': dft20 over f, twiddle W+^{mq}, deposit at slot m*16+q
        dft20<1>(v, tws);
        float* re = sRe + c*CSTR;
        float* im = sIm + c*CSTR;
        #pragma unroll
        for (int m = 0; m < 20; m++){
            float2 w = cmul(v[m], twf<1>(tws, m*q));
            re[m*16 + q] = w.x;
            im[m*16 + q] = w.y;
        }
    }
    __syncthreads();

    // inverse stage B'': all 320 threads, m in [0,20)
    {
        int m = tid >> 4;
        const float* re = sRe + c*CSTR;
        const float* im = sIm + c*CSTR;
        #pragma unroll
        for (int kq = 0; kq < 16; kq++){
            v[kq].x = re[m*16 + kq];
            v[kq].y = im[m*16 + kq];
        }
        dft16<1>(v, tws);
        float so = (m & 1) ? -S320 : S320;
        float* po = out + pb + col0 + c;
        #pragma unroll
        for (int j = 0; j < 16; j++){
            size_t ro = (size_t)(m + 20*j)*NSZ;
            po[ro]        = v[j].x*so;
            po[NPIX + ro] = v[j].y*so;
        }
    }
}

// ----------- fused TV prox (register 2x2 patches) + warp-Haar + momentum
#define RG 42
#define IS2 0.70710678118654752f
static __device__ __forceinline__ float softf(float v){
    float m = fabsf(v) - 0.005f;
    m = fmaxf(m, 0.f);
    return copysignf(m, v);
}

__global__ void __launch_bounds__(448, 3) tvwav_kernel(const float* __restrict__ in,
                                                       const float* __restrict__ xold,
                                                       float* __restrict__ xnew,
                                                       float* __restrict__ znew,
                                                       float beta)
{
    __shared__ float sUL [RG*21];
    __shared__ float sUT [21*43];
    __shared__ float sPxR[RG*21];
    __shared__ float sPyB[21*43];
    __shared__ float sw  [32*33];

    int tid = threadIdx.x;
    bool act = tid < 441;
    int pr = tid / 21, pc = tid - pr*21;
    int ri = 2*pr, rj = 2*pc;
    int plane = blockIdx.z;
    int gx0 = blockIdx.x*32 - 5;
    int gy0 = blockIdx.y*32 - 5;
    int base = plane * NPIX;
    int gi0 = gy0 + ri, gj0 = gx0 + rj;

    float x[2][2], u[2][2], px[2][2], py[2][2];

    if (act){
        #pragma unroll
        for (int i = 0; i < 2; i++){
            #pragma unroll
            for (int j = 0; j < 2; j++){
                int gi = gi0 + i, gj = gj0 + j;
                float v = 0.f;
                if ((unsigned)gi < NSZ && (unsigned)gj < NSZ) v = in[base + gi*NSZ + gj];
                x[i][j] = v; u[i][j] = v;
                px[i][j] = 0.f; py[i][j] = 0.f;
            }
        }
        sUL[ ri   *21 + pc] = u[0][0];
        sUL[(ri+1)*21 + pc] = u[1][0];
        sUT[pr*43 + rj    ] = u[0][0];
        sUT[pr*43 + rj + 1] = u[0][1];
    }
    __syncthreads();

    const float lam = 0.005f, tau = 0.25f;
    #pragma unroll 1
    for (int it = 0; it < 5; it++){
        if (act){
            bool xok1 = (rj + 1 < RG-1) && (gj0 + 1 < NSZ-1);
            bool yok1 = (ri + 1 < RG-1) && (gi0 + 1 < NSZ-1);
            float uR0 = xok1 ? sUL[ ri   *21 + pc + 1] : 0.f;
            float uR1 = xok1 ? sUL[(ri+1)*21 + pc + 1] : 0.f;
            float uD0 = yok1 ? sUT[(pr+1)*43 + rj    ] : 0.f;
            float uD1 = yok1 ? sUT[(pr+1)*43 + rj + 1] : 0.f;
            #pragma unroll
            for (int i = 0; i < 2; i++){
                #pragma unroll
                for (int j = 0; j < 2; j++){
                    bool xok = (j == 0) ? ((gj0 < NSZ-1)) : xok1;
                    bool yok = (i == 0) ? ((gi0 < NSZ-1)) : yok1;
                    float gx = 0.f, gy = 0.f;
                    if (xok) gx = ((j == 0) ? u[i][1] : ((i == 0) ? uR0 : uR1)) - u[i][j];
                    if (yok) gy = ((i == 0) ? u[1][j] : ((j == 0) ? uD0 : uD1)) - u[i][j];
                    float pnx = fmaf(tau, gx, px[i][j]);
                    float pny = fmaf(tau, gy, py[i][j]);
                    float s  = fmaf(pnx, pnx, fmaf(pny, pny, 1e-8f));
                    float sc = (s > 1.f) ? rsqrtf(s) : 1.f;
                    px[i][j] = pnx*sc;
                    py[i][j] = pny*sc;
                }
            }
            sPxR[ ri   *21 + pc] = px[0][1];
            sPxR[(ri+1)*21 + pc] = px[1][1];
            sPyB[pr*43 + rj    ] = py[1][0];
            sPyB[pr*43 + rj + 1] = py[1][1];
        }
        __syncthreads();
        if (act){
            float pxL0 = (pc > 0) ? sPxR[ ri   *21 + pc - 1] : 0.f;
            float pxL1 = (pc > 0) ? sPxR[(ri+1)*21 + pc - 1] : 0.f;
            float pyU0 = (pr > 0) ? sPyB[(pr-1)*43 + rj    ] : 0.f;
            float pyU1 = (pr > 0) ? sPyB[(pr-1)*43 + rj + 1] : 0.f;
            #pragma unroll
            for (int i = 0; i < 2; i++){
                #pragma unroll
                for (int j = 0; j < 2; j++){
                    float pxl = (j == 1) ? px[i][0] : ((i == 0) ? pxL0 : pxL1);
                    float pyu = (i == 1) ? py[0][j] : ((j == 0) ? pyU0 : pyU1);
                    int gj = gj0 + j, gi = gi0 + i;
                    float dvx = (gj == 0) ? px[i][j] : ((gj == NSZ-1) ? -pxl : px[i][j] - pxl);
                    float dvy = (gi == 0) ? py[i][j] : ((gi == NSZ-1) ? -pyu : py[i][j] - pyu);
                    u[i][j] = x[i][j] - lam*(dvx + dvy);
                }
            }
        }
        if (it < 4){
            if (act){
                sUL[ ri   *21 + pc] = u[0][0];
                sUL[(ri+1)*21 + pc] = u[1][0];
                sUT[pr*43 + rj    ] = u[0][0];
                sUT[pr*43 + rj + 1] = u[0][1];
            }
            __syncthreads();
        }
    }

    if (act){
        #pragma unroll
        for (int i = 0; i < 2; i++){
            #pragma unroll
            for (int j = 0; j < 2; j++){
                int ti = ri + i - 5, tj = rj + j - 5;
                if (ti >= 0 && ti < 32 && tj >= 0 && tj < 32)
                    sw[ti*33 + tj] = u[i][j];
            }
        }
    }
    __syncthreads();

    {
        const unsigned FM = 0xffffffffu;
        int lane = tid & 31;
        int warp = tid >> 5;
        int l = lane & 15;
        int qi = l >> 2, qj = l & 3;
        int pi = qi & 1, pj = qj & 1;
        int Pi = (qi >> 1) & 1, Pj = (qj >> 1) & 1;
        for (int blk = warp; blk < 16; blk += 14){
            int r0 = (blk >> 2)*8 + 2*qi;
            int c0 = (blk & 3)*8 + 2*qj;
            float p00 = sw[r0*33 + c0],     p01 = sw[r0*33 + c0 + 1];
            float p10 = sw[(r0+1)*33 + c0], p11 = sw[(r0+1)*33 + c0 + 1];
            float s0 = (p00 + p01)*IS2, d0 = (p00 - p01)*IS2;
            float s1 = (p10 + p11)*IS2, d1 = (p10 - p11)*IS2;
            float ll1 = (s0 + s1)*IS2;
            float lh1 = softf((s0 - s1)*IS2);
            float hl1 = softf((d0 + d1)*IS2);
            float hh1 = softf((d0 - d1)*IS2);
            float b  = __shfl_xor_sync(FM, ll1, 1);
            float cl = (ll1 + b)*IS2;
            float cd = (pj ? (b - ll1) : (ll1 - b))*IS2;
            float rl = __shfl_xor_sync(FM, cl, 4);
            float rd = __shfl_xor_sync(FM, cd, 4);
            float ll2 = (cl + rl)*IS2;
            float lh2 = softf((pi ? (rl - cl) : (cl - rl))*IS2);
            float hl2 = softf((cd + rd)*IS2);
            float hh2 = softf((pi ? (rd - cd) : (cd - rd))*IS2);
            float b3  = __shfl_xor_sync(FM, ll2, 2);
            float cl3 = (ll2 + b3)*IS2;
            float cd3 = (Pj ? (b3 - ll2) : (ll2 - b3))*IS2;
            float rl3 = __shfl_xor_sync(FM, cl3, 8);
            float rd3 = __shfl_xor_sync(FM, cd3, 8);
            float ll3 = (cl3 + rl3)*IS2;
            float lh3 = softf((Pi ? (rl3 - cl3) : (cl3 - rl3))*IS2);
            float hl3 = softf((cd3 + rd3)*IS2);
            float hh3 = softf((Pi ? (rd3 - cd3) : (cd3 - rd3))*IS2);
            float s3 = (Pi ? (ll3 - lh3) : (ll3 + lh3))*IS2;
            float d3 = (Pi ? (hl3 - hh3) : (hl3 + hh3))*IS2;
            float ll2r = (Pj ? (s3 - d3) : (s3 + d3))*IS2;
            float s2 = (pi ? (ll2r - lh2) : (ll2r + lh2))*IS2;
            float d2 = (pi ? (hl2 - hh2) : (hl2 + hh2))*IS2;
            float ll1r = (pj ? (s2 - d2) : (s2 + d2))*IS2;
            float sa = (ll1r + lh1)*IS2, sb = (ll1r - lh1)*IS2;
            float da = (hl1 + hh1)*IS2, db = (hl1 - hh1)*IS2;
            float q00 = (sa + da)*IS2, q01 = (sa - da)*IS2;
            float q10 = (sb + db)*IS2, q11 = (sb - db)*IS2;
            if (lane < 16){
                int gi = gy0 + 5 + r0, gj = gx0 + 5 + c0;
                int g = base + gi*NSZ + gj;
                float2 xo0 = *reinterpret_cast<const float2*>(xold + g);
                float2 xo1 = *reinterpret_cast<const float2*>(xold + g + NSZ);
                *reinterpret_cast<float2*>(xnew + g)       = make_float2(q00, q01);
                *reinterpret_cast<float2*>(xnew + g + NSZ) = make_float2(q10, q11);
                *reinterpret_cast<float2*>(znew + g) =
                    make_float2(q00 + beta*(q00 - xo0.x), q01 + beta*(q01 - xo0.y));
                *reinterpret_cast<float2*>(znew + g + NSZ) =
                    make_float2(q10 + beta*(q10 - xo1.x), q11 + beta*(q11 - xo1.y));
            }
        }
    }
}

// ----------------------------- host ------------------------------------
extern "C" void kernel_launch(void* const* d_in, const int* in_sizes, int n_in,
                              void* d_out, int out_size)
{
    const float* y    = (const float*)d_in[0];
    const float* mask = (const float*)d_in[1];
    float* out = (float*)d_out;
    float *z, *x, *t1, *t2;
    cudaGetSymbolAddress((void**)&z,   g_z);
    cudaGetSymbolAddress((void**)&x,   g_x);
    cudaGetSymbolAddress((void**)&t1,  g_t1);
    cudaGetSymbolAddress((void**)&t2,  g_t2);

    init_tw_kernel<<<1, 320>>>();

    // x0 = z0 = ifft2c(y)
    fft_col_init<<<BATCH*20, 320>>>(y, t1);
    fft_row_kernel<1,true ><<<BATCH*40, 160>>>(t1, x, z);

    double tt = 1.0;
    for (int it = 0; it < 15; it++){
        fft_row_kernel<0,false><<<BATCH*40, 160>>>(z, t1, nullptr);
        fft_col_combine<<<BATCH*20, 320>>>(t1, y, mask, t2);
        fft_row_kernel<1,false><<<BATCH*40, 160>>>(t2, t1, nullptr);
        double tn = 0.5*(1.0 + sqrt(1.0 + 4.0*tt*tt));
        float beta = (float)((tt - 1.0)/tn);
        float* xdst = (it == 14) ? out : x;
        tvwav_kernel<<<dim3(10,10,32), 448>>>(t1, x, xdst, z, beta);
        tt = tn;
    }
}